// round 8
// baseline (speedup 1.0000x reference)
#include <cuda_runtime.h>
#include <cuda_bf16.h>
#include <cstdint>

#define BB 4
#define LL 4096
#define DD 1024
#define MM 512
#define CH 16
#define CHLEN 32

typedef unsigned long long u64;
typedef unsigned int u32;

// ---------------- scratch (static device arrays; no runtime alloc) ----------
__device__ float g_smoothed[BB * MM * DD];      // 8 MB
__device__ int   g_pbidx[BB * LL];              // 64 KB
__device__ float g_chainA[BB * CH];
__device__ float g_chainB[BB * CH * DD];        // 256 KB
__device__ u32   g_atf[BB * LL * DD];           // 64 MB: enc, tf32 bits, k-pair permuted
__device__ u32   g_wtf[DD * DD];                // 4 MB:  W,   tf32 bits, k-pair permuted

__device__ __forceinline__ u32 smem_u32(const void* p) {
    u32 a;
    asm("{ .reg .u64 t; cvta.to.shared.u64 t, %1; cvt.u32.u64 %0, t; }" : "=r"(a) : "l"(p));
    return a;
}
__device__ __forceinline__ u32 f2tf32(float v) {
    u32 r;
    asm("cvt.rna.tf32.f32 %0, %1;" : "=r"(r) : "f"(v));
    return r;
}

// ---------------------------------------------------------------------------
// preconv8: fp32 -> tf32 bits, permuting each 8-elem k-group to
// [k0,k4,k1,k5,k2,k6,k3,k7] so fragment (k, k+4) pairs are adjacent (LDS.64).
// ---------------------------------------------------------------------------
__global__ void preconv8(const float* __restrict__ x, u32* __restrict__ y, int n8)
{
    int i = blockIdx.x * blockDim.x + threadIdx.x;
    if (i >= n8) return;
    float4 v0 = ((const float4*)x)[i * 2];
    float4 v1 = ((const float4*)x)[i * 2 + 1];
    uint4 o0, o1;
    o0.x = f2tf32(v0.x); o0.y = f2tf32(v1.x); o0.z = f2tf32(v0.y); o0.w = f2tf32(v1.y);
    o1.x = f2tf32(v0.z); o1.y = f2tf32(v1.z); o1.z = f2tf32(v0.w); o1.w = f2tf32(v1.w);
    ((uint4*)y)[i * 2]     = o0;
    ((uint4*)y)[i * 2 + 1] = o1;
}

// ---------------------------------------------------------------------------
// EMA phase 1: per-chunk local scan (h_in = 0), write h_local + chunk summary.
// ---------------------------------------------------------------------------
__global__ void ema1(const float* __restrict__ ct, const float* __restrict__ bp,
                     const int* __restrict__ bidx)
{
    const int c = blockIdx.x, b = blockIdx.y, d = threadIdx.x;
    __shared__ float p[CHLEN];
    const bool is64 = (bidx[1] == 0 && bidx[3] == 0);
    if (d < CHLEN) {
        int w = b * MM + c * CHLEN + d;
        if (is64) w <<= 1;
        p[d] = fmaxf(bp[b * LL + bidx[w]], 0.1f);
    }
    __syncthreads();

    const float* cb = ct + ((size_t)(b * MM + c * CHLEN)) * DD + d;
    float* sb = g_smoothed + ((size_t)(b * MM + c * CHLEN)) * DD + d;
    float h = 0.0f;
    int i0 = 0;
    if (c == 0) { h = cb[0]; sb[0] = h; i0 = 1; }
    for (int i = i0; i < CHLEN; i++) {
        float pm = p[i];
        float a = fmaxf(1.0f - pm, 1e-7f);
        h = a * h + pm * cb[(size_t)i * DD];
        sb[(size_t)i * DD] = h;
    }
    g_chainB[(b * CH + c) * DD + d] = h;
    if (d == 0) {
        float A = 1.0f;
        for (int i = i0; i < CHLEN; i++) A *= fmaxf(1.0f - p[i], 1e-7f);
        g_chainA[b * CH + c] = A;
    }
}

// ---------------------------------------------------------------------------
// EMA phase 2: fold chunk summaries -> h_in, add prefix*h_in to local scans.
// ---------------------------------------------------------------------------
__global__ void ema2(const float* __restrict__ bp, const int* __restrict__ bidx)
{
    const int c = blockIdx.x + 1, b = blockIdx.y, d = threadIdx.x;
    __shared__ float p[CHLEN];
    __shared__ float Aj[CH];
    const bool is64 = (bidx[1] == 0 && bidx[3] == 0);
    if (d < CHLEN) {
        int w = b * MM + c * CHLEN + d;
        if (is64) w <<= 1;
        p[d] = fmaxf(bp[b * LL + bidx[w]], 0.1f);
    }
    if (d >= 32 && d < 32 + CH) Aj[d - 32] = g_chainA[b * CH + (d - 32)];
    __syncthreads();

    float hin = 0.0f;
    for (int j = 0; j < c; j++)
        hin = Aj[j] * hin + g_chainB[(b * CH + j) * DD + d];

    float* sb = g_smoothed + ((size_t)(b * MM + c * CHLEN)) * DD + d;
    float pref = 1.0f;
    for (int i = 0; i < CHLEN; i++) {
        pref *= fmaxf(1.0f - p[i], 1e-7f);
        sb[(size_t)i * DD] += pref * hin;
    }
}

// ---------------------------------------------------------------------------
// plug_back_idx = clip(cumsum(bp >= 0.5) - 1, 0)
// ---------------------------------------------------------------------------
__global__ void pbidx_kernel(const float* __restrict__ bp)
{
    const int b = blockIdx.x, t = threadIdx.x;
    __shared__ int s[1024];
    const float* row = bp + b * LL;
    int loc[4];
    int cnt = 0;
#pragma unroll
    for (int i = 0; i < 4; i++) {
        cnt += (row[t * 4 + i] >= 0.5f) ? 1 : 0;
        loc[i] = cnt;
    }
    s[t] = cnt;
    __syncthreads();
    for (int off = 1; off < 1024; off <<= 1) {
        int add = (t >= off) ? s[t - off] : 0;
        __syncthreads();
        s[t] += add;
        __syncthreads();
    }
    int excl = s[t] - cnt;
#pragma unroll
    for (int i = 0; i < 4; i++) {
        int v = excl + loc[i] - 1;
        g_pbidx[b * LL + t * 4 + i] = v < 0 ? 0 : v;
    }
}

// ---------------------------------------------------------------------------
// TF32 GEMM (pre-rounded, k-pair-permuted) + fused plugback epilogue.
// Block tile 128(m) x 256(n); 512 threads, 16 warps (2m x 8n), warp 64x32.
// K-chunk 32, double-buffered cp.async; 40-word row stride (LDS.64
// conflict-free). L2 traffic: 0.79 GB (A fetched by 4 col-CTAs instead of 8).
// ---------------------------------------------------------------------------
#define KC 32
#define NCHUNK 32
#define RSW 40                           // row stride in words
#define A_TILE_B (128 * RSW * 4)         // 20480
#define B_TILE_B (256 * RSW * 4)         // 40960
#define STAGE_B  (A_TILE_B + B_TILE_B)   // 61440
#define SMEM_TOT (2 * STAGE_B)           // 122880

__device__ __forceinline__ void load_chunk(int t, u32 stA, u32 stB,
                                           int rowBase, int colBase, int tid)
{
    const int k0 = t * KC;
#pragma unroll
    for (int it = 0; it < 2; it++) {          // A: 128 rows x 8 x 16B = 1024
        int c = tid + it * 512;
        int row = c >> 3, cc = c & 7;
        u32 dst = stA + row * (RSW * 4) + cc * 16;
        const void* src = g_atf + ((size_t)(rowBase + row) << 10) + k0 + cc * 4;
        asm volatile("cp.async.cg.shared.global [%0], [%1], 16;" :: "r"(dst), "l"(src));
    }
#pragma unroll
    for (int it = 0; it < 4; it++) {          // B: 256 rows x 8 x 16B = 2048
        int c = tid + it * 512;
        int row = c >> 3, cc = c & 7;
        u32 dst = stB + row * (RSW * 4) + cc * 16;
        const void* src = g_wtf + ((size_t)(colBase + row) << 10) + k0 + cc * 4;
        asm volatile("cp.async.cg.shared.global [%0], [%1], 16;" :: "r"(dst), "l"(src));
    }
    asm volatile("cp.async.commit_group;");
}

__global__ void __launch_bounds__(512, 1)
gemm_tf32(float* __restrict__ out)
{
    extern __shared__ char smem[];
    const u32 sbase = smem_u32(smem);
    const int tid = threadIdx.x;
    const int wid = tid >> 5, lane = tid & 31;
    const int rowBase = blockIdx.y * 128;
    const int colBase = blockIdx.x * 256;
    const int wm = (wid >> 3) * 64;          // 2 m-warps
    const int wn = (wid & 7) * 32;           // 8 n-warps
    const int g = lane >> 2, tq = lane & 3;

    const u32 stA[2] = { sbase,              sbase + STAGE_B };
    const u32 stB[2] = { sbase + A_TILE_B,   sbase + STAGE_B + A_TILE_B };

    float acc[4][4][4];
#pragma unroll
    for (int i = 0; i < 4; i++)
#pragma unroll
        for (int j = 0; j < 4; j++)
#pragma unroll
            for (int k = 0; k < 4; k++) acc[i][j][k] = 0.0f;

    load_chunk(0, stA[0], stB[0], rowBase, colBase, tid);

    for (int t = 0; t < NCHUNK; t++) {
        if (t + 1 < NCHUNK) {
            load_chunk(t + 1, stA[(t + 1) & 1], stB[(t + 1) & 1],
                       rowBase, colBase, tid);
            asm volatile("cp.async.wait_group 1;");
        } else {
            asm volatile("cp.async.wait_group 0;");
        }
        __syncthreads();

        const u32* saw = (const u32*)(smem + (size_t)((t & 1) ? STAGE_B : 0));
        const u32* sbw = (const u32*)(smem + (size_t)((t & 1) ? STAGE_B + A_TILE_B
                                                              : A_TILE_B));
        const u32* pa = saw + (wm + g) * RSW;
        const u32* pb = sbw + (wn + g) * RSW;

#pragma unroll
        for (int ks = 0; ks < 4; ks++) {
            const int kk2 = ks * 8 + tq * 2;   // permuted pair (k, k+4)
            u32 a[4][4];
#pragma unroll
            for (int mi = 0; mi < 4; mi++) {
                uint2 lo = *(const uint2*)(pa + (mi * 16)     * RSW + kk2);
                uint2 hi = *(const uint2*)(pa + (mi * 16 + 8) * RSW + kk2);
                a[mi][0] = lo.x; a[mi][1] = hi.x; a[mi][2] = lo.y; a[mi][3] = hi.y;
            }
            u32 bf[4][2];
#pragma unroll
            for (int n8 = 0; n8 < 4; n8++) {
                uint2 bb = *(const uint2*)(pb + (n8 * 8) * RSW + kk2);
                bf[n8][0] = bb.x; bf[n8][1] = bb.y;
            }
#pragma unroll
            for (int mi = 0; mi < 4; mi++)
#pragma unroll
                for (int n8 = 0; n8 < 4; n8++) {
                    asm volatile(
                        "mma.sync.aligned.m16n8k8.row.col.f32.tf32.tf32.f32 "
                        "{%0,%1,%2,%3}, {%4,%5,%6,%7}, {%8,%9}, {%0,%1,%2,%3};"
                        : "+f"(acc[mi][n8][0]), "+f"(acc[mi][n8][1]),
                          "+f"(acc[mi][n8][2]), "+f"(acc[mi][n8][3])
                        : "r"(a[mi][0]), "r"(a[mi][1]), "r"(a[mi][2]), "r"(a[mi][3]),
                          "r"(bf[n8][0]), "r"(bf[n8][1]));
                }
        }
        __syncthreads();
    }

    // Epilogue: acc d0,d1 -> row g, cols 2tq,2tq+1 ; d2,d3 -> row g+8
#pragma unroll
    for (int mi = 0; mi < 4; mi++) {
#pragma unroll
        for (int half = 0; half < 2; half++) {
            const int row = rowBase + wm + mi * 16 + g + half * 8;
            const int b = row >> 12;
            const int idx = g_pbidx[row];
            const float* sp = g_smoothed + ((size_t)(b * MM + idx)) * DD;
            float* op = out + (size_t)row * DD;
#pragma unroll
            for (int n8 = 0; n8 < 4; n8++) {
                const int col = colBase + wn + n8 * 8 + tq * 2;
                float2 pv = *(const float2*)(sp + col);
                float2 ov;
                ov.x = acc[mi][n8][half * 2 + 0] + pv.x;
                ov.y = acc[mi][n8][half * 2 + 1] + pv.y;
                *(float2*)(op + col) = ov;
            }
        }
    }
}

// ---------------------------------------------------------------------------
// Launch
// ---------------------------------------------------------------------------
extern "C" void kernel_launch(void* const* d_in, const int* in_sizes, int n_in,
                              void* d_out, int out_size)
{
    const float* ct = nullptr;
    const float* enc = nullptr;
    const float* bp = nullptr;
    const int* bidx = nullptr;
    const float* Wm = nullptr;

    for (int i = 0; i < n_in; i++) {
        switch (in_sizes[i]) {
            case BB * MM * DD: ct  = (const float*)d_in[i]; break;
            case BB * LL * DD: enc = (const float*)d_in[i]; break;
            case BB * LL:      bp  = (const float*)d_in[i]; break;
            case DD * DD:      Wm  = (const float*)d_in[i]; break;
            case BB * MM:      if (!bidx) bidx = (const int*)d_in[i]; break;
            default: break;
        }
    }
    float* out = (float*)d_out;

    static u32* atf_p = nullptr;
    static u32* wtf_p = nullptr;
    if (!atf_p) {
        cudaGetSymbolAddress((void**)&atf_p, g_atf);
        cudaGetSymbolAddress((void**)&wtf_p, g_wtf);
        cudaFuncSetAttribute(gemm_tf32, cudaFuncAttributeMaxDynamicSharedMemorySize,
                             SMEM_TOT);
    }

    preconv8<<<(BB * LL * DD / 8 + 255) / 256, 256>>>(enc, atf_p, BB * LL * DD / 8);
    preconv8<<<(DD * DD / 8 + 255) / 256, 256>>>(Wm, wtf_p, DD * DD / 8);
    ema1<<<dim3(CH, BB), 1024>>>(ct, bp, bidx);
    ema2<<<dim3(CH - 1, BB), 1024>>>(bp, bidx);
    pbidx_kernel<<<BB, 1024>>>(bp);

    dim3 grid(DD / 256, (BB * LL) / 128);   // (4, 128)
    gemm_tf32<<<grid, 512, SMEM_TOT>>>(out);
}

// round 9
// speedup vs baseline: 1.0698x; 1.0698x over previous
#include <cuda_runtime.h>
#include <cuda_bf16.h>
#include <cstdint>

#define BB 4
#define LL 4096
#define DD 1024
#define MM 512
#define CH 16
#define CHLEN 32

typedef unsigned long long u64;
typedef unsigned int u32;

// ---------------- scratch (static device arrays; no runtime alloc) ----------
__device__ float g_smoothed[BB * MM * DD];      // 8 MB
__device__ int   g_pbidx[BB * LL];              // 64 KB
__device__ float g_chainA[BB * CH];
__device__ float g_chainB[BB * CH * DD];        // 256 KB
__device__ u32   g_atf[BB * LL * DD];           // 64 MB: enc tf32 bits, 16-k perm
__device__ u32   g_wtf[DD * DD];                // 4 MB:  W   tf32 bits, 16-k perm

__device__ __forceinline__ u32 smem_u32(const void* p) {
    u32 a;
    asm("{ .reg .u64 t; cvta.to.shared.u64 t, %1; cvt.u32.u64 %0, t; }" : "=r"(a) : "l"(p));
    return a;
}
__device__ __forceinline__ u32 f2tf32(float v) {
    u32 r;
    asm("cvt.rna.tf32.f32 %0, %1;" : "=r"(r) : "f"(v));
    return r;
}

// ---------------------------------------------------------------------------
// preconv16: fp32 -> tf32 bits, permuting each 16-elem k-group to
// [k0,k4,k8,k12, k1,k5,k9,k13, k2,k6,k10,k14, k3,k7,k11,k15] so one uint4
// holds a lane's (k, k+4, k+8, k+12) — two ks-steps of fragments per LDS.128.
// ---------------------------------------------------------------------------
__global__ void preconv16(const float* __restrict__ x, u32* __restrict__ y, int n16)
{
    int i = blockIdx.x * blockDim.x + threadIdx.x;
    if (i >= n16) return;
    float4 v0 = ((const float4*)x)[i * 4 + 0];
    float4 v1 = ((const float4*)x)[i * 4 + 1];
    float4 v2 = ((const float4*)x)[i * 4 + 2];
    float4 v3 = ((const float4*)x)[i * 4 + 3];
    uint4 o0, o1, o2, o3;
    o0.x = f2tf32(v0.x); o0.y = f2tf32(v1.x); o0.z = f2tf32(v2.x); o0.w = f2tf32(v3.x);
    o1.x = f2tf32(v0.y); o1.y = f2tf32(v1.y); o1.z = f2tf32(v2.y); o1.w = f2tf32(v3.y);
    o2.x = f2tf32(v0.z); o2.y = f2tf32(v1.z); o2.z = f2tf32(v2.z); o2.w = f2tf32(v3.z);
    o3.x = f2tf32(v0.w); o3.y = f2tf32(v1.w); o3.z = f2tf32(v2.w); o3.w = f2tf32(v3.w);
    ((uint4*)y)[i * 4 + 0] = o0;
    ((uint4*)y)[i * 4 + 1] = o1;
    ((uint4*)y)[i * 4 + 2] = o2;
    ((uint4*)y)[i * 4 + 3] = o3;
}

// ---------------------------------------------------------------------------
// EMA phase 1: per-chunk local scan. grid (CH, BB, 4), block 256 (d-split).
// ---------------------------------------------------------------------------
__global__ void ema1(const float* __restrict__ ct, const float* __restrict__ bp,
                     const int* __restrict__ bidx)
{
    const int c = blockIdx.x, b = blockIdx.y;
    const int d = blockIdx.z * 256 + threadIdx.x;
    __shared__ float p[CHLEN];
    const bool is64 = (bidx[1] == 0 && bidx[3] == 0);
    if (threadIdx.x < CHLEN) {
        int w = b * MM + c * CHLEN + threadIdx.x;
        if (is64) w <<= 1;
        p[threadIdx.x] = fmaxf(bp[b * LL + bidx[w]], 0.1f);
    }
    __syncthreads();

    const float* cb = ct + ((size_t)(b * MM + c * CHLEN)) * DD + d;
    float* sb = g_smoothed + ((size_t)(b * MM + c * CHLEN)) * DD + d;
    float h = 0.0f;
    int i0 = 0;
    if (c == 0) { h = cb[0]; sb[0] = h; i0 = 1; }
#pragma unroll 8
    for (int i = i0; i < CHLEN; i++) {
        float pm = p[i];
        float a = fmaxf(1.0f - pm, 1e-7f);
        h = a * h + pm * cb[(size_t)i * DD];
        sb[(size_t)i * DD] = h;
    }
    g_chainB[(b * CH + c) * DD + d] = h;
    if (blockIdx.z == 0 && threadIdx.x == 0) {
        float A = 1.0f;
        for (int i = i0; i < CHLEN; i++) A *= fmaxf(1.0f - p[i], 1e-7f);
        g_chainA[b * CH + c] = A;
    }
}

// ---------------------------------------------------------------------------
// EMA phase 2: fold chunk summaries. grid (CH-1, BB, 4), block 256.
// ---------------------------------------------------------------------------
__global__ void ema2(const float* __restrict__ bp, const int* __restrict__ bidx)
{
    const int c = blockIdx.x + 1, b = blockIdx.y;
    const int d = blockIdx.z * 256 + threadIdx.x;
    __shared__ float p[CHLEN];
    __shared__ float Aj[CH];
    const bool is64 = (bidx[1] == 0 && bidx[3] == 0);
    if (threadIdx.x < CHLEN) {
        int w = b * MM + c * CHLEN + threadIdx.x;
        if (is64) w <<= 1;
        p[threadIdx.x] = fmaxf(bp[b * LL + bidx[w]], 0.1f);
    }
    if (threadIdx.x >= 32 && threadIdx.x < 32 + CH)
        Aj[threadIdx.x - 32] = g_chainA[b * CH + (threadIdx.x - 32)];
    __syncthreads();

    float hin = 0.0f;
    for (int j = 0; j < c; j++)
        hin = Aj[j] * hin + g_chainB[(b * CH + j) * DD + d];

    float* sb = g_smoothed + ((size_t)(b * MM + c * CHLEN)) * DD + d;
    float pref = 1.0f;
#pragma unroll 8
    for (int i = 0; i < CHLEN; i++) {
        pref *= fmaxf(1.0f - p[i], 1e-7f);
        sb[(size_t)i * DD] += pref * hin;
    }
}

// ---------------------------------------------------------------------------
// plug_back_idx = clip(cumsum(bp >= 0.5) - 1, 0)
// ---------------------------------------------------------------------------
__global__ void pbidx_kernel(const float* __restrict__ bp)
{
    const int b = blockIdx.x, t = threadIdx.x;
    __shared__ int s[1024];
    const float* row = bp + b * LL;
    int loc[4];
    int cnt = 0;
#pragma unroll
    for (int i = 0; i < 4; i++) {
        cnt += (row[t * 4 + i] >= 0.5f) ? 1 : 0;
        loc[i] = cnt;
    }
    s[t] = cnt;
    __syncthreads();
    for (int off = 1; off < 1024; off <<= 1) {
        int add = (t >= off) ? s[t - off] : 0;
        __syncthreads();
        s[t] += add;
        __syncthreads();
    }
    int excl = s[t] - cnt;
#pragma unroll
    for (int i = 0; i < 4; i++) {
        int v = excl + loc[i] - 1;
        g_pbidx[b * LL + t * 4 + i] = v < 0 ? 0 : v;
    }
}

// ---------------------------------------------------------------------------
// TF32 GEMM (pre-rounded, 16-k-permuted) + fused plugback epilogue.
// Block 128x128, 8 warps (2m x 4n), warp tile 64x32, KC=32, double buffer.
// Fragments via LDS.128: one uint4 = two ks-steps. Row stride 48 words
// (192B): LDS.128 8-lane phases hit banks (16g+4tq) mod 32 -> conflict-free.
// ---------------------------------------------------------------------------
#define KC 32
#define NCHUNK 32
#define RSW 48                         // row stride in words
#define TILE_B (128 * RSW * 4)         // 24576 per tile
#define STAGE_B (2 * TILE_B)           // 49152 (A + B)
#define SMEM_TOT (2 * STAGE_B)         // 98304

__device__ __forceinline__ void load_chunk(int t, u32 stA, u32 stB,
                                           int rowBase, int colBase, int tid)
{
    const int k0 = t * KC;
#pragma unroll
    for (int it = 0; it < 4; it++) {
        int c = tid + it * 256;
        int row = c >> 3, cc = c & 7;
        u32 dst = stA + row * (RSW * 4) + cc * 16;
        const void* src = g_atf + ((size_t)(rowBase + row) << 10) + k0 + cc * 4;
        asm volatile("cp.async.cg.shared.global [%0], [%1], 16;" :: "r"(dst), "l"(src));
    }
#pragma unroll
    for (int it = 0; it < 4; it++) {
        int c = tid + it * 256;
        int row = c >> 3, cc = c & 7;
        u32 dst = stB + row * (RSW * 4) + cc * 16;
        const void* src = g_wtf + ((size_t)(colBase + row) << 10) + k0 + cc * 4;
        asm volatile("cp.async.cg.shared.global [%0], [%1], 16;" :: "r"(dst), "l"(src));
    }
    asm volatile("cp.async.commit_group;");
}

__global__ void __launch_bounds__(256, 2)
gemm_tf32(float* __restrict__ out)
{
    extern __shared__ char smem[];
    const u32 sbase = smem_u32(smem);
    const int tid = threadIdx.x;
    const int wid = tid >> 5, lane = tid & 31;
    const int rowBase = blockIdx.y * 128;
    const int colBase = blockIdx.x * 128;
    const int wm = (wid >> 2) * 64;         // 2 m-warps
    const int wn = (wid & 3) * 32;          // 4 n-warps
    const int g = lane >> 2, tq = lane & 3;

    const u32 stA[2] = { sbase,              sbase + STAGE_B };
    const u32 stB[2] = { sbase + TILE_B,     sbase + STAGE_B + TILE_B };

    float acc[4][4][4];
#pragma unroll
    for (int i = 0; i < 4; i++)
#pragma unroll
        for (int j = 0; j < 4; j++)
#pragma unroll
            for (int k = 0; k < 4; k++) acc[i][j][k] = 0.0f;

    load_chunk(0, stA[0], stB[0], rowBase, colBase, tid);

    for (int t = 0; t < NCHUNK; t++) {
        if (t + 1 < NCHUNK) {
            load_chunk(t + 1, stA[(t + 1) & 1], stB[(t + 1) & 1],
                       rowBase, colBase, tid);
            asm volatile("cp.async.wait_group 1;");
        } else {
            asm volatile("cp.async.wait_group 0;");
        }
        __syncthreads();

        const u32* saw = (const u32*)(smem + (size_t)((t & 1) ? STAGE_B : 0));
        const u32* sbw = saw + TILE_B / 4;
        const u32* pa = saw + (wm + g) * RSW + tq * 4;
        const u32* pb = sbw + (wn + g) * RSW + tq * 4;

#pragma unroll
        for (int grp = 0; grp < 2; grp++) {     // two 16-k groups per chunk
            const int base = grp * 16;
            uint4 alo[4], ahi[4];
#pragma unroll
            for (int mi = 0; mi < 4; mi++) {
                alo[mi] = *(const uint4*)(pa + (mi * 16)     * RSW + base);
                ahi[mi] = *(const uint4*)(pa + (mi * 16 + 8) * RSW + base);
            }
            uint4 bb[4];
#pragma unroll
            for (int n8 = 0; n8 < 4; n8++)
                bb[n8] = *(const uint4*)(pb + (n8 * 8) * RSW + base);

            // ks = 2*grp   : A = {alo.x, ahi.x, alo.y, ahi.y}, B = {bb.x, bb.y}
#pragma unroll
            for (int mi = 0; mi < 4; mi++)
#pragma unroll
                for (int n8 = 0; n8 < 4; n8++)
                    asm volatile(
                        "mma.sync.aligned.m16n8k8.row.col.f32.tf32.tf32.f32 "
                        "{%0,%1,%2,%3}, {%4,%5,%6,%7}, {%8,%9}, {%0,%1,%2,%3};"
                        : "+f"(acc[mi][n8][0]), "+f"(acc[mi][n8][1]),
                          "+f"(acc[mi][n8][2]), "+f"(acc[mi][n8][3])
                        : "r"(alo[mi].x), "r"(ahi[mi].x),
                          "r"(alo[mi].y), "r"(ahi[mi].y),
                          "r"(bb[n8].x), "r"(bb[n8].y));
            // ks = 2*grp+1 : A = {alo.z, ahi.z, alo.w, ahi.w}, B = {bb.z, bb.w}
#pragma unroll
            for (int mi = 0; mi < 4; mi++)
#pragma unroll
                for (int n8 = 0; n8 < 4; n8++)
                    asm volatile(
                        "mma.sync.aligned.m16n8k8.row.col.f32.tf32.tf32.f32 "
                        "{%0,%1,%2,%3}, {%4,%5,%6,%7}, {%8,%9}, {%0,%1,%2,%3};"
                        : "+f"(acc[mi][n8][0]), "+f"(acc[mi][n8][1]),
                          "+f"(acc[mi][n8][2]), "+f"(acc[mi][n8][3])
                        : "r"(alo[mi].z), "r"(ahi[mi].z),
                          "r"(alo[mi].w), "r"(ahi[mi].w),
                          "r"(bb[n8].z), "r"(bb[n8].w));
        }
        __syncthreads();
    }

    // Epilogue: acc d0,d1 -> row g, cols 2tq,2tq+1 ; d2,d3 -> row g+8
#pragma unroll
    for (int mi = 0; mi < 4; mi++) {
#pragma unroll
        for (int half = 0; half < 2; half++) {
            const int row = rowBase + wm + mi * 16 + g + half * 8;
            const int b = row >> 12;
            const int idx = g_pbidx[row];
            const float* sp = g_smoothed + ((size_t)(b * MM + idx)) * DD;
            float* op = out + (size_t)row * DD;
#pragma unroll
            for (int n8 = 0; n8 < 4; n8++) {
                const int col = colBase + wn + n8 * 8 + tq * 2;
                float2 pv = *(const float2*)(sp + col);
                float2 ov;
                ov.x = acc[mi][n8][half * 2 + 0] + pv.x;
                ov.y = acc[mi][n8][half * 2 + 1] + pv.y;
                *(float2*)(op + col) = ov;
            }
        }
    }
}

// ---------------------------------------------------------------------------
// Launch
// ---------------------------------------------------------------------------
extern "C" void kernel_launch(void* const* d_in, const int* in_sizes, int n_in,
                              void* d_out, int out_size)
{
    const float* ct = nullptr;
    const float* enc = nullptr;
    const float* bp = nullptr;
    const int* bidx = nullptr;
    const float* Wm = nullptr;

    for (int i = 0; i < n_in; i++) {
        switch (in_sizes[i]) {
            case BB * MM * DD: ct  = (const float*)d_in[i]; break;
            case BB * LL * DD: enc = (const float*)d_in[i]; break;
            case BB * LL:      bp  = (const float*)d_in[i]; break;
            case DD * DD:      Wm  = (const float*)d_in[i]; break;
            case BB * MM:      if (!bidx) bidx = (const int*)d_in[i]; break;
            default: break;
        }
    }
    float* out = (float*)d_out;

    static u32* atf_p = nullptr;
    static u32* wtf_p = nullptr;
    if (!atf_p) {
        cudaGetSymbolAddress((void**)&atf_p, g_atf);
        cudaGetSymbolAddress((void**)&wtf_p, g_wtf);
        cudaFuncSetAttribute(gemm_tf32, cudaFuncAttributeMaxDynamicSharedMemorySize,
                             SMEM_TOT);
    }

    preconv16<<<(BB * LL * DD / 16 + 255) / 256, 256>>>(enc, atf_p, BB * LL * DD / 16);
    preconv16<<<(DD * DD / 16 + 255) / 256, 256>>>(Wm, wtf_p, DD * DD / 16);
    ema1<<<dim3(CH, BB, 4), 256>>>(ct, bp, bidx);
    ema2<<<dim3(CH - 1, BB, 4), 256>>>(bp, bidx);
    pbidx_kernel<<<BB, 1024>>>(bp);

    dim3 grid(DD / 128, (BB * LL) / 128);   // (8, 128)
    gemm_tf32<<<grid, 256, SMEM_TOT>>>(out);
}

// round 10
// speedup vs baseline: 1.1846x; 1.1072x over previous
#include <cuda_runtime.h>
#include <cuda_bf16.h>
#include <cstdint>

#define BB 4
#define LL 4096
#define DD 1024
#define MM 512
#define CH 16
#define CHLEN 32

typedef unsigned long long u64;
typedef unsigned int u32;

// ---------------- scratch (static device arrays; no runtime alloc) ----------
__device__ float g_smoothed[BB * MM * DD];      // 8 MB
__device__ int   g_pbidx[BB * LL];              // 64 KB
__device__ float g_chainA[BB * CH];
__device__ float g_chainB[BB * CH * DD];        // 256 KB
__device__ u32   g_atf[BB * LL * DD];           // 64 MB: enc, tf32 bits, k-pair permuted
__device__ u32   g_wtf[DD * DD];                // 4 MB:  W,   tf32 bits, k-pair permuted

__device__ __forceinline__ u32 smem_u32(const void* p) {
    u32 a;
    asm("{ .reg .u64 t; cvta.to.shared.u64 t, %1; cvt.u32.u64 %0, t; }" : "=r"(a) : "l"(p));
    return a;
}
__device__ __forceinline__ u32 f2tf32(float v) {
    u32 r;
    asm("cvt.rna.tf32.f32 %0, %1;" : "=r"(r) : "f"(v));
    return r;
}

// ---------------------------------------------------------------------------
// preconv_all: fp32 -> tf32 bits for BOTH enc and W in one launch, permuting
// each 8-elem k-group to [k0,k4,k1,k5,k2,k6,k3,k7] so fragment (k, k+4)
// pairs are adjacent (LDS.64 in the GEMM).
// ---------------------------------------------------------------------------
#define N8_ENC (BB * LL * DD / 8)   // 2097152
#define N8_W   (DD * DD / 8)        // 131072

__global__ void preconv_all(const float* __restrict__ enc,
                            const float* __restrict__ Wm,
                            u32* __restrict__ atf, u32* __restrict__ wtf)
{
    int i = blockIdx.x * blockDim.x + threadIdx.x;
    const float* x;
    u32* y;
    int j;
    if (i < N8_ENC)              { x = enc; y = atf; j = i; }
    else if (i < N8_ENC + N8_W)  { x = Wm;  y = wtf; j = i - N8_ENC; }
    else return;

    float4 v0 = ((const float4*)x)[j * 2];
    float4 v1 = ((const float4*)x)[j * 2 + 1];
    uint4 o0, o1;
    o0.x = f2tf32(v0.x); o0.y = f2tf32(v1.x); o0.z = f2tf32(v0.y); o0.w = f2tf32(v1.y);
    o1.x = f2tf32(v0.z); o1.y = f2tf32(v1.z); o1.z = f2tf32(v0.w); o1.w = f2tf32(v1.w);
    ((uint4*)y)[j * 2]     = o0;
    ((uint4*)y)[j * 2 + 1] = o1;
}

// ---------------------------------------------------------------------------
// EMA phase 1 (R7 version): per-chunk local scan, 1024-thread blocks.
// ---------------------------------------------------------------------------
__global__ void ema1(const float* __restrict__ ct, const float* __restrict__ bp,
                     const int* __restrict__ bidx)
{
    const int c = blockIdx.x, b = blockIdx.y, d = threadIdx.x;
    __shared__ float p[CHLEN];
    const bool is64 = (bidx[1] == 0 && bidx[3] == 0);
    if (d < CHLEN) {
        int w = b * MM + c * CHLEN + d;
        if (is64) w <<= 1;
        p[d] = fmaxf(bp[b * LL + bidx[w]], 0.1f);
    }
    __syncthreads();

    const float* cb = ct + ((size_t)(b * MM + c * CHLEN)) * DD + d;
    float* sb = g_smoothed + ((size_t)(b * MM + c * CHLEN)) * DD + d;
    float h = 0.0f;
    int i0 = 0;
    if (c == 0) { h = cb[0]; sb[0] = h; i0 = 1; }
    for (int i = i0; i < CHLEN; i++) {
        float pm = p[i];
        float a = fmaxf(1.0f - pm, 1e-7f);
        h = a * h + pm * cb[(size_t)i * DD];
        sb[(size_t)i * DD] = h;
    }
    g_chainB[(b * CH + c) * DD + d] = h;
    if (d == 0) {
        float A = 1.0f;
        for (int i = i0; i < CHLEN; i++) A *= fmaxf(1.0f - p[i], 1e-7f);
        g_chainA[b * CH + c] = A;
    }
}

// ---------------------------------------------------------------------------
// EMA phase 2 (R7 version): fold chunk summaries -> h_in, add prefix*h_in.
// ---------------------------------------------------------------------------
__global__ void ema2(const float* __restrict__ bp, const int* __restrict__ bidx)
{
    const int c = blockIdx.x + 1, b = blockIdx.y, d = threadIdx.x;
    __shared__ float p[CHLEN];
    __shared__ float Aj[CH];
    const bool is64 = (bidx[1] == 0 && bidx[3] == 0);
    if (d < CHLEN) {
        int w = b * MM + c * CHLEN + d;
        if (is64) w <<= 1;
        p[d] = fmaxf(bp[b * LL + bidx[w]], 0.1f);
    }
    if (d >= 32 && d < 32 + CH) Aj[d - 32] = g_chainA[b * CH + (d - 32)];
    __syncthreads();

    float hin = 0.0f;
    for (int j = 0; j < c; j++)
        hin = Aj[j] * hin + g_chainB[(b * CH + j) * DD + d];

    float* sb = g_smoothed + ((size_t)(b * MM + c * CHLEN)) * DD + d;
    float pref = 1.0f;
    for (int i = 0; i < CHLEN; i++) {
        pref *= fmaxf(1.0f - p[i], 1e-7f);
        sb[(size_t)i * DD] += pref * hin;
    }
}

// ---------------------------------------------------------------------------
// plug_back_idx = clip(cumsum(bp >= 0.5) - 1, 0)
// ---------------------------------------------------------------------------
__global__ void pbidx_kernel(const float* __restrict__ bp)
{
    const int b = blockIdx.x, t = threadIdx.x;
    __shared__ int s[1024];
    const float* row = bp + b * LL;
    int loc[4];
    int cnt = 0;
#pragma unroll
    for (int i = 0; i < 4; i++) {
        cnt += (row[t * 4 + i] >= 0.5f) ? 1 : 0;
        loc[i] = cnt;
    }
    s[t] = cnt;
    __syncthreads();
    for (int off = 1; off < 1024; off <<= 1) {
        int add = (t >= off) ? s[t - off] : 0;
        __syncthreads();
        s[t] += add;
        __syncthreads();
    }
    int excl = s[t] - cnt;
#pragma unroll
    for (int i = 0; i < 4; i++) {
        int v = excl + loc[i] - 1;
        g_pbidx[b * LL + t * 4 + i] = v < 0 ? 0 : v;
    }
}

// ---------------------------------------------------------------------------
// TF32 GEMM (R7 version, proven best): pre-rounded k-pair-permuted operands,
// block 128x128, 8 warps (2m x 4n), warp tile 64x32, KC=32, double buffer,
// 40-word row stride (LDS.64 conflict-free), 2 CTAs/SM, fused plugback.
// ---------------------------------------------------------------------------
#define KC 32
#define NCHUNK 32
#define RSW 40                         // row stride in words
#define TILE_B (128 * RSW * 4)         // 20480 per tile
#define STAGE_B (2 * TILE_B)           // 40960 (A + B)
#define SMEM_TOT (2 * STAGE_B)         // 81920

__device__ __forceinline__ void load_chunk(int t, u32 stA, u32 stB,
                                           int rowBase, int colBase, int tid)
{
    const int k0 = t * KC;
#pragma unroll
    for (int it = 0; it < 4; it++) {
        int c = tid + it * 256;
        int row = c >> 3, cc = c & 7;
        u32 dst = stA + row * (RSW * 4) + cc * 16;
        const void* src = g_atf + ((size_t)(rowBase + row) << 10) + k0 + cc * 4;
        asm volatile("cp.async.cg.shared.global [%0], [%1], 16;" :: "r"(dst), "l"(src));
    }
#pragma unroll
    for (int it = 0; it < 4; it++) {
        int c = tid + it * 256;
        int row = c >> 3, cc = c & 7;
        u32 dst = stB + row * (RSW * 4) + cc * 16;
        const void* src = g_wtf + ((size_t)(colBase + row) << 10) + k0 + cc * 4;
        asm volatile("cp.async.cg.shared.global [%0], [%1], 16;" :: "r"(dst), "l"(src));
    }
    asm volatile("cp.async.commit_group;");
}

__global__ void __launch_bounds__(256, 2)
gemm_tf32(float* __restrict__ out)
{
    extern __shared__ char smem[];
    const u32 sbase = smem_u32(smem);
    const int tid = threadIdx.x;
    const int wid = tid >> 5, lane = tid & 31;
    const int rowBase = blockIdx.y * 128;
    const int colBase = blockIdx.x * 128;
    const int wm = (wid >> 2) * 64;         // 2 m-warps
    const int wn = (wid & 3) * 32;          // 4 n-warps
    const int g = lane >> 2, tq = lane & 3;

    const u32 stA[2] = { sbase,              sbase + STAGE_B };
    const u32 stB[2] = { sbase + TILE_B,     sbase + STAGE_B + TILE_B };

    float acc[4][4][4];
#pragma unroll
    for (int i = 0; i < 4; i++)
#pragma unroll
        for (int j = 0; j < 4; j++)
#pragma unroll
            for (int k = 0; k < 4; k++) acc[i][j][k] = 0.0f;

    load_chunk(0, stA[0], stB[0], rowBase, colBase, tid);

    for (int t = 0; t < NCHUNK; t++) {
        if (t + 1 < NCHUNK) {
            load_chunk(t + 1, stA[(t + 1) & 1], stB[(t + 1) & 1],
                       rowBase, colBase, tid);
            asm volatile("cp.async.wait_group 1;");
        } else {
            asm volatile("cp.async.wait_group 0;");
        }
        __syncthreads();

        const u32* saw = (const u32*)(smem + (size_t)((t & 1) ? STAGE_B : 0));
        const u32* sbw = (const u32*)(smem + (size_t)((t & 1) ? STAGE_B + TILE_B : TILE_B));
        const u32* pa = saw + (wm + g) * RSW;
        const u32* pb = sbw + (wn + g) * RSW;

#pragma unroll
        for (int ks = 0; ks < 4; ks++) {
            const int kk2 = ks * 8 + tq * 2;   // permuted pair (k, k+4)
            u32 a[4][4];
#pragma unroll
            for (int mi = 0; mi < 4; mi++) {
                uint2 lo = *(const uint2*)(pa + (mi * 16)     * RSW + kk2);
                uint2 hi = *(const uint2*)(pa + (mi * 16 + 8) * RSW + kk2);
                a[mi][0] = lo.x; a[mi][1] = hi.x; a[mi][2] = lo.y; a[mi][3] = hi.y;
            }
            u32 bf[4][2];
#pragma unroll
            for (int n8 = 0; n8 < 4; n8++) {
                uint2 bb = *(const uint2*)(pb + (n8 * 8) * RSW + kk2);
                bf[n8][0] = bb.x; bf[n8][1] = bb.y;
            }
#pragma unroll
            for (int mi = 0; mi < 4; mi++)
#pragma unroll
                for (int n8 = 0; n8 < 4; n8++) {
                    asm volatile(
                        "mma.sync.aligned.m16n8k8.row.col.f32.tf32.tf32.f32 "
                        "{%0,%1,%2,%3}, {%4,%5,%6,%7}, {%8,%9}, {%0,%1,%2,%3};"
                        : "+f"(acc[mi][n8][0]), "+f"(acc[mi][n8][1]),
                          "+f"(acc[mi][n8][2]), "+f"(acc[mi][n8][3])
                        : "r"(a[mi][0]), "r"(a[mi][1]), "r"(a[mi][2]), "r"(a[mi][3]),
                          "r"(bf[n8][0]), "r"(bf[n8][1]));
                }
        }
        __syncthreads();
    }

    // Epilogue: acc d0,d1 -> row g, cols 2tq,2tq+1 ; d2,d3 -> row g+8
#pragma unroll
    for (int mi = 0; mi < 4; mi++) {
#pragma unroll
        for (int half = 0; half < 2; half++) {
            const int row = rowBase + wm + mi * 16 + g + half * 8;
            const int b = row >> 12;
            const int idx = g_pbidx[row];
            const float* sp = g_smoothed + ((size_t)(b * MM + idx)) * DD;
            float* op = out + (size_t)row * DD;
#pragma unroll
            for (int n8 = 0; n8 < 4; n8++) {
                const int col = colBase + wn + n8 * 8 + tq * 2;
                float2 pv = *(const float2*)(sp + col);
                float2 ov;
                ov.x = acc[mi][n8][half * 2 + 0] + pv.x;
                ov.y = acc[mi][n8][half * 2 + 1] + pv.y;
                *(float2*)(op + col) = ov;
            }
        }
    }
}

// ---------------------------------------------------------------------------
// Launch: graph fork — preconv on main stream, EMA chain on side stream,
// join before the GEMM. Streams/events created once (first, non-captured call).
// ---------------------------------------------------------------------------
extern "C" void kernel_launch(void* const* d_in, const int* in_sizes, int n_in,
                              void* d_out, int out_size)
{
    const float* ct = nullptr;
    const float* enc = nullptr;
    const float* bp = nullptr;
    const int* bidx = nullptr;
    const float* Wm = nullptr;

    for (int i = 0; i < n_in; i++) {
        switch (in_sizes[i]) {
            case BB * MM * DD: ct  = (const float*)d_in[i]; break;
            case BB * LL * DD: enc = (const float*)d_in[i]; break;
            case BB * LL:      bp  = (const float*)d_in[i]; break;
            case DD * DD:      Wm  = (const float*)d_in[i]; break;
            case BB * MM:      if (!bidx) bidx = (const int*)d_in[i]; break;
            default: break;
        }
    }
    float* out = (float*)d_out;

    static u32* atf_p = nullptr;
    static u32* wtf_p = nullptr;
    static cudaStream_t s2 = nullptr;
    static cudaEvent_t evF = nullptr, evJ = nullptr;
    if (!atf_p) {
        cudaGetSymbolAddress((void**)&atf_p, g_atf);
        cudaGetSymbolAddress((void**)&wtf_p, g_wtf);
        cudaFuncSetAttribute(gemm_tf32, cudaFuncAttributeMaxDynamicSharedMemorySize,
                             SMEM_TOT);
        cudaStreamCreateWithFlags(&s2, cudaStreamNonBlocking);
        cudaEventCreateWithFlags(&evF, cudaEventDisableTiming);
        cudaEventCreateWithFlags(&evJ, cudaEventDisableTiming);
    }

    // Fork: side stream joins the capture via event wait.
    cudaEventRecord(evF, 0);
    cudaStreamWaitEvent(s2, evF, 0);

    // Branch A (main stream): operand conversion for the GEMM.
    preconv_all<<<(N8_ENC + N8_W + 255) / 256, 256>>>(enc, Wm, atf_p, wtf_p);

    // Branch B (side stream): EMA smoothing chain + plugback indices.
    ema1<<<dim3(CH, BB), 1024, 0, s2>>>(ct, bp, bidx);
    ema2<<<dim3(CH - 1, BB), 1024, 0, s2>>>(bp, bidx);
    pbidx_kernel<<<BB, 1024, 0, s2>>>(bp);

    // Join: GEMM (epilogue reads g_smoothed / g_pbidx) waits on both branches.
    cudaEventRecord(evJ, s2);
    cudaStreamWaitEvent(0, evJ, 0);

    dim3 grid(DD / 128, (BB * LL) / 128);   // (8, 128)
    gemm_tf32<<<grid, 256, SMEM_TOT>>>(out);
}

// round 11
// speedup vs baseline: 1.3128x; 1.1082x over previous
#include <cuda_runtime.h>
#include <cuda_bf16.h>
#include <cstdint>

#define BB 4
#define LL 4096
#define DD 1024
#define MM 512
#define CH 16
#define CHLEN 32

typedef unsigned long long u64;
typedef unsigned int u32;

// ---------------- scratch (static device arrays; no runtime alloc) ----------
__device__ float g_smoothed[BB * MM * DD];      // 8 MB
__device__ int   g_pbidx[BB * LL];              // 64 KB
__device__ float g_chainA[BB * CH];
__device__ float g_chainB[BB * CH * DD];        // 256 KB
__device__ u32   g_atf[BB * LL * DD];           // 64 MB: enc, tf32 bits, k-pair permuted
__device__ u32   g_wtf[DD * DD];                // 4 MB:  W,   tf32 bits, k-pair permuted

__device__ __forceinline__ u32 smem_u32(const void* p) {
    u32 a;
    asm("{ .reg .u64 t; cvta.to.shared.u64 t, %1; cvt.u32.u64 %0, t; }" : "=r"(a) : "l"(p));
    return a;
}
__device__ __forceinline__ u32 f2tf32(float v) {
    u32 r;
    asm("cvt.rna.tf32.f32 %0, %1;" : "=r"(r) : "f"(v));
    return r;
}

// ---------------------------------------------------------------------------
// preconv_all: fp32 -> tf32 bits for BOTH enc and W in one launch, permuting
// each 8-elem k-group to [k0,k4,k1,k5,k2,k6,k3,k7] (fragment pairs adjacent).
// ---------------------------------------------------------------------------
#define N8_ENC (BB * LL * DD / 8)   // 2097152
#define N8_W   (DD * DD / 8)        // 131072

__global__ void preconv_all(const float* __restrict__ enc,
                            const float* __restrict__ Wm,
                            u32* __restrict__ atf, u32* __restrict__ wtf)
{
    int i = blockIdx.x * blockDim.x + threadIdx.x;
    const float* x;
    u32* y;
    int j;
    if (i < N8_ENC)              { x = enc; y = atf; j = i; }
    else if (i < N8_ENC + N8_W)  { x = Wm;  y = wtf; j = i - N8_ENC; }
    else return;

    float4 v0 = ((const float4*)x)[j * 2];
    float4 v1 = ((const float4*)x)[j * 2 + 1];
    uint4 o0, o1;
    o0.x = f2tf32(v0.x); o0.y = f2tf32(v1.x); o0.z = f2tf32(v0.y); o0.w = f2tf32(v1.y);
    o1.x = f2tf32(v0.z); o1.y = f2tf32(v1.z); o1.z = f2tf32(v0.w); o1.w = f2tf32(v1.w);
    ((uint4*)y)[j * 2]     = o0;
    ((uint4*)y)[j * 2 + 1] = o1;
}

// ---------------------------------------------------------------------------
// EMA phase 1: per-chunk local scan, 1024-thread blocks (R7/R10 version).
// ---------------------------------------------------------------------------
__global__ void ema1(const float* __restrict__ ct, const float* __restrict__ bp,
                     const int* __restrict__ bidx)
{
    const int c = blockIdx.x, b = blockIdx.y, d = threadIdx.x;
    __shared__ float p[CHLEN];
    const bool is64 = (bidx[1] == 0 && bidx[3] == 0);
    if (d < CHLEN) {
        int w = b * MM + c * CHLEN + d;
        if (is64) w <<= 1;
        p[d] = fmaxf(bp[b * LL + bidx[w]], 0.1f);
    }
    __syncthreads();

    const float* cb = ct + ((size_t)(b * MM + c * CHLEN)) * DD + d;
    float* sb = g_smoothed + ((size_t)(b * MM + c * CHLEN)) * DD + d;
    float h = 0.0f;
    int i0 = 0;
    if (c == 0) { h = cb[0]; sb[0] = h; i0 = 1; }
    for (int i = i0; i < CHLEN; i++) {
        float pm = p[i];
        float a = fmaxf(1.0f - pm, 1e-7f);
        h = a * h + pm * cb[(size_t)i * DD];
        sb[(size_t)i * DD] = h;
    }
    g_chainB[(b * CH + c) * DD + d] = h;
    if (d == 0) {
        float A = 1.0f;
        for (int i = i0; i < CHLEN; i++) A *= fmaxf(1.0f - p[i], 1e-7f);
        g_chainA[b * CH + c] = A;
    }
}

// ---------------------------------------------------------------------------
// EMA phase 2: fold chunk summaries -> h_in, add prefix*h_in to local scans.
// ---------------------------------------------------------------------------
__global__ void ema2(const float* __restrict__ bp, const int* __restrict__ bidx)
{
    const int c = blockIdx.x + 1, b = blockIdx.y, d = threadIdx.x;
    __shared__ float p[CHLEN];
    __shared__ float Aj[CH];
    const bool is64 = (bidx[1] == 0 && bidx[3] == 0);
    if (d < CHLEN) {
        int w = b * MM + c * CHLEN + d;
        if (is64) w <<= 1;
        p[d] = fmaxf(bp[b * LL + bidx[w]], 0.1f);
    }
    if (d >= 32 && d < 32 + CH) Aj[d - 32] = g_chainA[b * CH + (d - 32)];
    __syncthreads();

    float hin = 0.0f;
    for (int j = 0; j < c; j++)
        hin = Aj[j] * hin + g_chainB[(b * CH + j) * DD + d];

    float* sb = g_smoothed + ((size_t)(b * MM + c * CHLEN)) * DD + d;
    float pref = 1.0f;
    for (int i = 0; i < CHLEN; i++) {
        pref *= fmaxf(1.0f - p[i], 1e-7f);
        sb[(size_t)i * DD] += pref * hin;
    }
}

// ---------------------------------------------------------------------------
// plug_back_idx = clip(cumsum(bp >= 0.5) - 1, 0)
// ---------------------------------------------------------------------------
__global__ void pbidx_kernel(const float* __restrict__ bp)
{
    const int b = blockIdx.x, t = threadIdx.x;
    __shared__ int s[1024];
    const float* row = bp + b * LL;
    int loc[4];
    int cnt = 0;
#pragma unroll
    for (int i = 0; i < 4; i++) {
        cnt += (row[t * 4 + i] >= 0.5f) ? 1 : 0;
        loc[i] = cnt;
    }
    s[t] = cnt;
    __syncthreads();
    for (int off = 1; off < 1024; off <<= 1) {
        int add = (t >= off) ? s[t - off] : 0;
        __syncthreads();
        s[t] += add;
        __syncthreads();
    }
    int excl = s[t] - cnt;
#pragma unroll
    for (int i = 0; i < 4; i++) {
        int v = excl + loc[i] - 1;
        g_pbidx[b * LL + t * 4 + i] = v < 0 ? 0 : v;
    }
}

// ---------------------------------------------------------------------------
// TF32 GEMM: rotation-swizzled smem (zero padding), 3-stage cp.async pipeline,
// ONE __syncthreads per chunk. Block 128x128, 8 warps (2m x 4n), warp 64x32.
// Swizzle: word (row,k) at column (k + 8*(row&3)) & 31. LDS.64 half-warp
// phase bank-pairs = 4*(ks + g&3) + tq mod 16 -> bijection, conflict-free.
// Fragment rows all have row&3 == g&3 -> swizzle offset constant per ks.
// ---------------------------------------------------------------------------
#define KC 32
#define NCHUNK 32
#define TILE_B 16384                   // 128 rows x 32 words x 4B
#define STAGE_B (2 * TILE_B)           // 32768 (A + B)
#define SMEM_TOT (3 * STAGE_B)         // 98304

__device__ __forceinline__ void load_chunk(int t, u32 stA, u32 stB,
                                           int rowBase, int colBase, int tid)
{
    const int k0 = t * KC;
#pragma unroll
    for (int it = 0; it < 4; it++) {
        int c = tid + it * 256;
        int row = c >> 3, cc = c & 7;
        u32 col = (u32)((cc * 4 + 8 * (row & 3)) & 31);
        u32 dst = stA + row * 128 + col * 4;
        const void* src = g_atf + ((size_t)(rowBase + row) << 10) + k0 + cc * 4;
        asm volatile("cp.async.cg.shared.global [%0], [%1], 16;" :: "r"(dst), "l"(src));
    }
#pragma unroll
    for (int it = 0; it < 4; it++) {
        int c = tid + it * 256;
        int row = c >> 3, cc = c & 7;
        u32 col = (u32)((cc * 4 + 8 * (row & 3)) & 31);
        u32 dst = stB + row * 128 + col * 4;
        const void* src = g_wtf + ((size_t)(colBase + row) << 10) + k0 + cc * 4;
        asm volatile("cp.async.cg.shared.global [%0], [%1], 16;" :: "r"(dst), "l"(src));
    }
    asm volatile("cp.async.commit_group;");
}

__global__ void __launch_bounds__(256, 2)
gemm_tf32(float* __restrict__ out)
{
    extern __shared__ char smem[];
    const u32 sbase = smem_u32(smem);
    const int tid = threadIdx.x;
    const int wid = tid >> 5, lane = tid & 31;
    const int rowBase = blockIdx.y * 128;
    const int colBase = blockIdx.x * 128;
    const int wm = (wid >> 2) * 64;         // 2 m-warps
    const int wn = (wid & 3) * 32;          // 4 n-warps
    const int g = lane >> 2, tq = lane & 3;
    const int rot = 8 * (g & 3);            // swizzle rotation for this lane

    float acc[4][4][4];
#pragma unroll
    for (int i = 0; i < 4; i++)
#pragma unroll
        for (int j = 0; j < 4; j++)
#pragma unroll
            for (int k = 0; k < 4; k++) acc[i][j][k] = 0.0f;

    load_chunk(0, sbase, sbase + TILE_B, rowBase, colBase, tid);
    load_chunk(1, sbase + STAGE_B, sbase + STAGE_B + TILE_B, rowBase, colBase, tid);

    int stage = 0;
    for (int t = 0; t < NCHUNK; t++) {
        if (t < NCHUNK - 1) asm volatile("cp.async.wait_group 1;");
        else                asm volatile("cp.async.wait_group 0;");
        __syncthreads();   // loads(t) visible; also releases stage (t-1)%3 for reuse

        const u32* saw = (const u32*)(smem + (size_t)stage * STAGE_B);
        const u32* sbw = saw + TILE_B / 4;
        const u32* pa = saw + (wm + g) * 32;
        const u32* pb = sbw + (wn + g) * 32;

#pragma unroll
        for (int ks = 0; ks < 4; ks++) {
            const int off = (ks * 8 + tq * 2 + rot) & 31;  // swizzled pair (k,k+4)
            u32 a[4][4];
#pragma unroll
            for (int mi = 0; mi < 4; mi++) {
                uint2 lo = *(const uint2*)(pa + (mi * 16)     * 32 + off);
                uint2 hi = *(const uint2*)(pa + (mi * 16 + 8) * 32 + off);
                a[mi][0] = lo.x; a[mi][1] = hi.x; a[mi][2] = lo.y; a[mi][3] = hi.y;
            }
            u32 bf[4][2];
#pragma unroll
            for (int n8 = 0; n8 < 4; n8++) {
                uint2 bb = *(const uint2*)(pb + (n8 * 8) * 32 + off);
                bf[n8][0] = bb.x; bf[n8][1] = bb.y;
            }
#pragma unroll
            for (int mi = 0; mi < 4; mi++)
#pragma unroll
                for (int n8 = 0; n8 < 4; n8++) {
                    asm volatile(
                        "mma.sync.aligned.m16n8k8.row.col.f32.tf32.tf32.f32 "
                        "{%0,%1,%2,%3}, {%4,%5,%6,%7}, {%8,%9}, {%0,%1,%2,%3};"
                        : "+f"(acc[mi][n8][0]), "+f"(acc[mi][n8][1]),
                          "+f"(acc[mi][n8][2]), "+f"(acc[mi][n8][3])
                        : "r"(a[mi][0]), "r"(a[mi][1]), "r"(a[mi][2]), "r"(a[mi][3]),
                          "r"(bf[n8][0]), "r"(bf[n8][1]));
                }
        }

        // Prefetch t+2 into stage (t+2)%3 == (t-1)%3 (safe: all warps passed
        // this chunk's __syncthreads, so compute(t-1) reads are done).
        if (t + 2 < NCHUNK) {
            int ps = stage + 2;
            if (ps >= 3) ps -= 3;
            load_chunk(t + 2, sbase + (u32)ps * STAGE_B,
                       sbase + (u32)ps * STAGE_B + TILE_B, rowBase, colBase, tid);
        }
        if (++stage == 3) stage = 0;
    }

    // Epilogue: acc d0,d1 -> row g, cols 2tq,2tq+1 ; d2,d3 -> row g+8
#pragma unroll
    for (int mi = 0; mi < 4; mi++) {
#pragma unroll
        for (int half = 0; half < 2; half++) {
            const int row = rowBase + wm + mi * 16 + g + half * 8;
            const int b = row >> 12;
            const int idx = g_pbidx[row];
            const float* sp = g_smoothed + ((size_t)(b * MM + idx)) * DD;
            float* op = out + (size_t)row * DD;
#pragma unroll
            for (int n8 = 0; n8 < 4; n8++) {
                const int col = colBase + wn + n8 * 8 + tq * 2;
                float2 pv = *(const float2*)(sp + col);
                float2 ov;
                ov.x = acc[mi][n8][half * 2 + 0] + pv.x;
                ov.y = acc[mi][n8][half * 2 + 1] + pv.y;
                *(float2*)(op + col) = ov;
            }
        }
    }
}

// ---------------------------------------------------------------------------
// Launch: graph fork — preconv on main stream, EMA chain on side stream,
// join before the GEMM (R10-proven pattern).
// ---------------------------------------------------------------------------
extern "C" void kernel_launch(void* const* d_in, const int* in_sizes, int n_in,
                              void* d_out, int out_size)
{
    const float* ct = nullptr;
    const float* enc = nullptr;
    const float* bp = nullptr;
    const int* bidx = nullptr;
    const float* Wm = nullptr;

    for (int i = 0; i < n_in; i++) {
        switch (in_sizes[i]) {
            case BB * MM * DD: ct  = (const float*)d_in[i]; break;
            case BB * LL * DD: enc = (const float*)d_in[i]; break;
            case BB * LL:      bp  = (const float*)d_in[i]; break;
            case DD * DD:      Wm  = (const float*)d_in[i]; break;
            case BB * MM:      if (!bidx) bidx = (const int*)d_in[i]; break;
            default: break;
        }
    }
    float* out = (float*)d_out;

    static u32* atf_p = nullptr;
    static u32* wtf_p = nullptr;
    static cudaStream_t s2 = nullptr;
    static cudaEvent_t evF = nullptr, evJ = nullptr;
    if (!atf_p) {
        cudaGetSymbolAddress((void**)&atf_p, g_atf);
        cudaGetSymbolAddress((void**)&wtf_p, g_wtf);
        cudaFuncSetAttribute(gemm_tf32, cudaFuncAttributeMaxDynamicSharedMemorySize,
                             SMEM_TOT);
        cudaStreamCreateWithFlags(&s2, cudaStreamNonBlocking);
        cudaEventCreateWithFlags(&evF, cudaEventDisableTiming);
        cudaEventCreateWithFlags(&evJ, cudaEventDisableTiming);
    }

    // Fork: side stream joins the capture via event wait.
    cudaEventRecord(evF, 0);
    cudaStreamWaitEvent(s2, evF, 0);

    // Branch A (main stream): operand conversion for the GEMM.
    preconv_all<<<(N8_ENC + N8_W + 255) / 256, 256>>>(enc, Wm, atf_p, wtf_p);

    // Branch B (side stream): EMA smoothing chain + plugback indices.
    ema1<<<dim3(CH, BB), 1024, 0, s2>>>(ct, bp, bidx);
    ema2<<<dim3(CH - 1, BB), 1024, 0, s2>>>(bp, bidx);
    pbidx_kernel<<<BB, 1024, 0, s2>>>(bp);

    // Join: GEMM (epilogue reads g_smoothed / g_pbidx) waits on both branches.
    cudaEventRecord(evJ, s2);
    cudaStreamWaitEvent(0, evJ, 0);

    dim3 grid(DD / 128, (BB * LL) / 128);   // (8, 128)
    gemm_tf32<<<grid, 256, SMEM_TOT>>>(out);
}